// round 1
// baseline (speedup 1.0000x reference)
#include <cuda_runtime.h>
#include <cstdint>

// ---------------------------------------------------------------------------
// Problem constants
// ---------------------------------------------------------------------------
#define Bb   32
#define Nn   512
#define Cc   32
#define NT   24
#define Hh   8
#define DH   48
#define Ee   384          // H*DH
#define INd  768          // C*NT
#define OUTd 768
#define E3   1152         // 3*E
#define Mrows (Bb*Nn)     // 16384

// ---------------------------------------------------------------------------
// Scratch (device globals; no runtime allocation allowed)
// ---------------------------------------------------------------------------
__device__ float g_qkv_t[(size_t)Mrows * E3];   // 75.5 MB
__device__ float g_qkv_s[(size_t)Mrows * E3];   // 75.5 MB
__device__ float g_xt[(size_t)Mrows * Ee];      // 25.2 MB
__device__ float g_xs[(size_t)Mrows * Ee];      // 25.2 MB
__device__ float g_alpha_in[Bb * 2 * Ee];       // (32, 768)
__device__ float g_gate0[Bb * Ee];
__device__ float g_gate1[Bb * Ee];

// ---------------------------------------------------------------------------
// Generic SGEMM:  C[M x N] = A[M x K] @ W[K x N] + bias[N]
// 128x128 block tile, K-tile 8, 256 threads, 8x8 per-thread (split 4+4).
// ---------------------------------------------------------------------------
__global__ __launch_bounds__(256, 2)
void sgemm_bias(const float* __restrict__ A, const float* __restrict__ W,
                const float* __restrict__ bias, float* __restrict__ C,
                int Md, int Nd, int Kd)
{
    __shared__ float As[8][128];
    __shared__ float Bs[8][128];

    const int tid = threadIdx.x;
    const int tx  = tid & 15;          // 0..15 -> columns
    const int ty  = tid >> 4;          // 0..15 -> rows
    const int rowBase = blockIdx.y * 128;
    const int colBase = blockIdx.x * 128;

    // A load: 128 rows x 8 cols -> each thread one float4
    const int aRow = tid >> 1;         // 0..127
    const int aCol = (tid & 1) * 4;    // 0 or 4
    // B load: 8 rows x 128 cols -> each thread one float4
    const int bRow = tid >> 5;         // 0..7
    const int bCol = (tid & 31) * 4;   // 0..124

    float acc[8][8];
#pragma unroll
    for (int i = 0; i < 8; ++i)
#pragma unroll
        for (int j = 0; j < 8; ++j) acc[i][j] = 0.0f;

    for (int k0 = 0; k0 < Kd; k0 += 8) {
        float4 a4 = *reinterpret_cast<const float4*>(
            &A[(size_t)(rowBase + aRow) * Kd + k0 + aCol]);
        As[aCol + 0][aRow] = a4.x;
        As[aCol + 1][aRow] = a4.y;
        As[aCol + 2][aRow] = a4.z;
        As[aCol + 3][aRow] = a4.w;
        *reinterpret_cast<float4*>(&Bs[bRow][bCol]) =
            *reinterpret_cast<const float4*>(
                &W[(size_t)(k0 + bRow) * Nd + colBase + bCol]);
        __syncthreads();

#pragma unroll
        for (int k = 0; k < 8; ++k) {
            float ra[8], rb[8];
            float4 t0 = *reinterpret_cast<const float4*>(&As[k][ty * 4]);
            float4 t1 = *reinterpret_cast<const float4*>(&As[k][64 + ty * 4]);
            ra[0]=t0.x; ra[1]=t0.y; ra[2]=t0.z; ra[3]=t0.w;
            ra[4]=t1.x; ra[5]=t1.y; ra[6]=t1.z; ra[7]=t1.w;
            float4 u0 = *reinterpret_cast<const float4*>(&Bs[k][tx * 4]);
            float4 u1 = *reinterpret_cast<const float4*>(&Bs[k][64 + tx * 4]);
            rb[0]=u0.x; rb[1]=u0.y; rb[2]=u0.z; rb[3]=u0.w;
            rb[4]=u1.x; rb[5]=u1.y; rb[6]=u1.z; rb[7]=u1.w;
#pragma unroll
            for (int i = 0; i < 8; ++i)
#pragma unroll
                for (int j = 0; j < 8; ++j)
                    acc[i][j] = fmaf(ra[i], rb[j], acc[i][j]);
        }
        __syncthreads();
    }

#pragma unroll
    for (int i = 0; i < 8; ++i) {
        int r = rowBase + (i < 4 ? ty * 4 + i : 64 + ty * 4 + (i - 4));
#pragma unroll
        for (int jg = 0; jg < 2; ++jg) {
            int c = colBase + (jg == 0 ? tx * 4 : 64 + tx * 4);
            float4 o;
            o.x = acc[i][jg*4 + 0] + bias[c + 0];
            o.y = acc[i][jg*4 + 1] + bias[c + 1];
            o.z = acc[i][jg*4 + 2] + bias[c + 2];
            o.w = acc[i][jg*4 + 3] + bias[c + 3];
            *reinterpret_cast<float4*>(&C[(size_t)r * Nd + c]) = o;
        }
    }
}

// ---------------------------------------------------------------------------
// Temporal attention (flash-style online softmax).
// grid (N/128, H, B), block 128. Thread owns one query row.
// qkv layout per row: [3][H][DH] ; output x_t layout per row: [H][DH]
// ---------------------------------------------------------------------------
__global__ __launch_bounds__(128)
void temporal_attn(const float* __restrict__ qkv, float* __restrict__ xt)
{
    __shared__ float Ks[64 * DH];
    __shared__ float Vs[64 * DH];

    const int b = blockIdx.z, h = blockIdx.y;
    const int n = blockIdx.x * 128 + threadIdx.x;
    const int tid = threadIdx.x;
    const float scale = 0.14433756729740643f; // 1/sqrt(48)

    float q[DH];
    {
        const float* qp = qkv + ((size_t)(b * Nn + n)) * E3 + h * DH;
#pragma unroll
        for (int d = 0; d < DH; ++d) q[d] = qp[d] * scale;
    }

    float o[DH];
#pragma unroll
    for (int d = 0; d < DH; ++d) o[d] = 0.0f;
    float m = -1e30f, l = 0.0f;

    for (int kt = 0; kt < Nn; kt += 64) {
        // load K/V tile (64 x 48)
        for (int i = tid; i < 64 * DH; i += 128) {
            int r = i / DH, c = i - r * DH;
            size_t base = ((size_t)(b * Nn + kt + r)) * E3 + h * DH + c;
            Ks[i] = qkv[base + Ee];        // K section
            Vs[i] = qkv[base + 2 * Ee];    // V section
        }
        __syncthreads();

#pragma unroll 4
        for (int j = 0; j < 64; ++j) {
            const float* kr = &Ks[j * DH];
            float s = 0.0f;
#pragma unroll
            for (int d = 0; d < DH; ++d) s = fmaf(q[d], kr[d], s);
            float mNew = fmaxf(m, s);
            float corr = __expf(m - mNew);
            float p    = __expf(s - mNew);
            l = fmaf(l, corr, p);
            const float* vr = &Vs[j * DH];
#pragma unroll
            for (int d = 0; d < DH; ++d)
                o[d] = fmaf(p, vr[d], o[d] * corr);
            m = mNew;
        }
        __syncthreads();
    }

    float inv = 1.0f / l;
    float* op = xt + ((size_t)(b * Nn + n)) * Ee + h * DH;
#pragma unroll
    for (int d = 0; d < DH; ++d) op[d] = o[d] * inv;
}

// ---------------------------------------------------------------------------
// Spatial attention: per g = b*n, per head: q,k,v are (cs=2, nt=24).
// attn[t,u] = softmax_u( sum_c q[c,t]*k[c,u] )  (unscaled)
// out[c,t]  = sum_u attn[t,u]*v[c,u]
// block = 256 (8 warps, warp = head), grid = 16384
// ---------------------------------------------------------------------------
__global__ __launch_bounds__(256)
void spatial_attn(const float* __restrict__ qkv, float* __restrict__ xs)
{
    __shared__ float sh[8][3 * DH];
    const int g = blockIdx.x;
    const int w = threadIdx.x >> 5, lane = threadIdx.x & 31;

    const float* base = qkv + (size_t)g * E3 + w * DH;
    for (int i = lane; i < 3 * DH; i += 32) {
        int sec = i / DH, idx = i - sec * DH;
        sh[w][i] = base[sec * Ee + idx];
    }
    __syncwarp();

    if (lane < NT) {
        const float* q = sh[w];
        const float* k = sh[w] + DH;
        const float* v = sh[w] + 2 * DH;
        float q0 = q[lane], q1 = q[NT + lane];
        float s[NT];
        float mx = -1e30f;
#pragma unroll
        for (int u = 0; u < NT; ++u) {
            s[u] = fmaf(q1, k[NT + u], q0 * k[u]);
            mx = fmaxf(mx, s[u]);
        }
        float sum = 0.0f;
#pragma unroll
        for (int u = 0; u < NT; ++u) { s[u] = __expf(s[u] - mx); sum += s[u]; }
        float inv = 1.0f / sum;
        float o0 = 0.0f, o1 = 0.0f;
#pragma unroll
        for (int u = 0; u < NT; ++u) {
            o0 = fmaf(s[u], v[u], o0);
            o1 = fmaf(s[u], v[NT + u], o1);
        }
        float* op = xs + (size_t)g * Ee + w * DH;
        op[lane]      = o0 * inv;
        op[NT + lane] = o1 * inv;
    }
}

// ---------------------------------------------------------------------------
// Mean over frames of concat([x_t, x_s]) -> (B, 768)
// block per b, 256 threads, 3 outputs each; coalesced over feature dim.
// ---------------------------------------------------------------------------
__global__ __launch_bounds__(256)
void mean_concat(const float* __restrict__ xt, const float* __restrict__ xs,
                 float* __restrict__ alphaIn)
{
    const int b = blockIdx.x, tid = threadIdx.x;
#pragma unroll
    for (int jj = 0; jj < 3; ++jj) {
        int j = tid + jj * 256;
        const float* src = (j < Ee)
            ? xt + (size_t)b * Nn * Ee + j
            : xs + (size_t)b * Nn * Ee + (j - Ee);
        float acc = 0.0f;
        for (int n = 0; n < Nn; ++n) acc += src[(size_t)n * Ee];
        alphaIn[b * 2 * Ee + j] = acc * (1.0f / (float)Nn);
    }
}

// ---------------------------------------------------------------------------
// Gating: row = alphaIn[b] @ Wts + bts; pairwise softmax over (E,2).
// block per b, 768 threads.
// ---------------------------------------------------------------------------
__global__ __launch_bounds__(768)
void gate_kernel(const float* __restrict__ alphaIn, const float* __restrict__ Wts,
                 const float* __restrict__ bts,
                 float* __restrict__ g0, float* __restrict__ g1)
{
    __shared__ float a[768];
    __shared__ float val[768];
    const int b = blockIdx.x, t = threadIdx.x;
    a[t] = alphaIn[b * 768 + t];
    __syncthreads();
    float acc = bts[t];
    for (int k = 0; k < 768; ++k)
        acc = fmaf(a[k], Wts[(size_t)k * 768 + t], acc);
    val[t] = acc;
    __syncthreads();
    if (t < Ee) {
        float v0 = val[2 * t], v1 = val[2 * t + 1];
        float mx = fmaxf(v0, v1);
        float e0 = __expf(v0 - mx), e1 = __expf(v1 - mx);
        float inv = 1.0f / (e0 + e1);
        g0[b * Ee + t] = e0 * inv;
        g1[b * Ee + t] = e1 * inv;
    }
}

// ---------------------------------------------------------------------------
// Fused output GEMM:
//   y = (x_t * g0[b]) @ Wfc_t + bfc_t + (x_s * g1[b]) @ Wfc_s + bfc_s
// Same 128x128 tiling; gate applied during the A-tile load (a 128-row tile
// never crosses a batch boundary since 512 % 128 == 0).
// ---------------------------------------------------------------------------
__global__ __launch_bounds__(256, 2)
void fused_out_gemm(const float* __restrict__ xt, const float* __restrict__ xs,
                    const float* __restrict__ g0, const float* __restrict__ g1,
                    const float* __restrict__ Wt, const float* __restrict__ Ws,
                    const float* __restrict__ bt, const float* __restrict__ bs,
                    float* __restrict__ out)
{
    __shared__ float As[8][128];
    __shared__ float Bs[8][128];

    const int tid = threadIdx.x;
    const int tx  = tid & 15;
    const int ty  = tid >> 4;
    const int rowBase = blockIdx.y * 128;
    const int colBase = blockIdx.x * 128;
    const int bIdx = rowBase >> 9;   // row / 512

    const int aRow = tid >> 1;
    const int aCol = (tid & 1) * 4;
    const int bRow = tid >> 5;
    const int bCol = (tid & 31) * 4;

    float acc[8][8];
#pragma unroll
    for (int i = 0; i < 8; ++i)
#pragma unroll
        for (int j = 0; j < 8; ++j) acc[i][j] = 0.0f;

    for (int pass = 0; pass < 2; ++pass) {
        const float* A    = pass ? xs : xt;
        const float* W    = pass ? Ws : Wt;
        const float* gate = (pass ? g1 : g0) + bIdx * Ee;

        for (int k0 = 0; k0 < Ee; k0 += 8) {
            float4 a4 = *reinterpret_cast<const float4*>(
                &A[(size_t)(rowBase + aRow) * Ee + k0 + aCol]);
            float4 s4 = *reinterpret_cast<const float4*>(&gate[k0 + aCol]);
            As[aCol + 0][aRow] = a4.x * s4.x;
            As[aCol + 1][aRow] = a4.y * s4.y;
            As[aCol + 2][aRow] = a4.z * s4.z;
            As[aCol + 3][aRow] = a4.w * s4.w;
            *reinterpret_cast<float4*>(&Bs[bRow][bCol]) =
                *reinterpret_cast<const float4*>(
                    &W[(size_t)(k0 + bRow) * OUTd + colBase + bCol]);
            __syncthreads();

#pragma unroll
            for (int k = 0; k < 8; ++k) {
                float ra[8], rb[8];
                float4 t0 = *reinterpret_cast<const float4*>(&As[k][ty * 4]);
                float4 t1 = *reinterpret_cast<const float4*>(&As[k][64 + ty * 4]);
                ra[0]=t0.x; ra[1]=t0.y; ra[2]=t0.z; ra[3]=t0.w;
                ra[4]=t1.x; ra[5]=t1.y; ra[6]=t1.z; ra[7]=t1.w;
                float4 u0 = *reinterpret_cast<const float4*>(&Bs[k][tx * 4]);
                float4 u1 = *reinterpret_cast<const float4*>(&Bs[k][64 + tx * 4]);
                rb[0]=u0.x; rb[1]=u0.y; rb[2]=u0.z; rb[3]=u0.w;
                rb[4]=u1.x; rb[5]=u1.y; rb[6]=u1.z; rb[7]=u1.w;
#pragma unroll
                for (int i = 0; i < 8; ++i)
#pragma unroll
                    for (int j = 0; j < 8; ++j)
                        acc[i][j] = fmaf(ra[i], rb[j], acc[i][j]);
            }
            __syncthreads();
        }
    }

#pragma unroll
    for (int i = 0; i < 8; ++i) {
        int r = rowBase + (i < 4 ? ty * 4 + i : 64 + ty * 4 + (i - 4));
#pragma unroll
        for (int jg = 0; jg < 2; ++jg) {
            int c = colBase + (jg == 0 ? tx * 4 : 64 + tx * 4);
            float4 o;
            o.x = acc[i][jg*4 + 0] + bt[c + 0] + bs[c + 0];
            o.y = acc[i][jg*4 + 1] + bt[c + 1] + bs[c + 1];
            o.z = acc[i][jg*4 + 2] + bt[c + 2] + bs[c + 2];
            o.w = acc[i][jg*4 + 3] + bt[c + 3] + bs[c + 3];
            *reinterpret_cast<float4*>(&out[(size_t)r * OUTd + c]) = o;
        }
    }
}

// ---------------------------------------------------------------------------
// Launch
// ---------------------------------------------------------------------------
extern "C" void kernel_launch(void* const* d_in, const int* in_sizes, int n_in,
                              void* d_out, int out_size)
{
    const float* x      = (const float*)d_in[0];
    const float* Wqkv_t = (const float*)d_in[1];
    const float* bqkv_t = (const float*)d_in[2];
    const float* Wqkv_s = (const float*)d_in[3];
    const float* bqkv_s = (const float*)d_in[4];
    const float* Wts    = (const float*)d_in[5];
    const float* bts    = (const float*)d_in[6];
    const float* Wfc_t  = (const float*)d_in[7];
    const float* bfc_t  = (const float*)d_in[8];
    const float* Wfc_s  = (const float*)d_in[9];
    const float* bfc_s  = (const float*)d_in[10];
    float* out = (float*)d_out;

    float *qkvT, *qkvS, *xt, *xs, *alphaIn, *g0, *g1;
    cudaGetSymbolAddress((void**)&qkvT,    g_qkv_t);
    cudaGetSymbolAddress((void**)&qkvS,    g_qkv_s);
    cudaGetSymbolAddress((void**)&xt,      g_xt);
    cudaGetSymbolAddress((void**)&xs,      g_xs);
    cudaGetSymbolAddress((void**)&alphaIn, g_alpha_in);
    cudaGetSymbolAddress((void**)&g0,      g_gate0);
    cudaGetSymbolAddress((void**)&g1,      g_gate1);

    // QKV projections (x viewed as (16384, 768))
    sgemm_bias<<<dim3(E3 / 128, Mrows / 128), 256>>>(x, Wqkv_t, bqkv_t, qkvT,
                                                     Mrows, E3, INd);
    sgemm_bias<<<dim3(E3 / 128, Mrows / 128), 256>>>(x, Wqkv_s, bqkv_s, qkvS,
                                                     Mrows, E3, INd);
    // Attentions
    temporal_attn<<<dim3(Nn / 128, Hh, Bb), 128>>>(qkvT, xt);
    spatial_attn<<<Mrows, 256>>>(qkvS, xs);
    // Gating
    mean_concat<<<Bb, 256>>>(xt, xs, alphaIn);
    gate_kernel<<<Bb, 768>>>(alphaIn, Wts, bts, g0, g1);
    // Fused gated output projection
    fused_out_gemm<<<dim3(OUTd / 128, Mrows / 128), 256>>>(xt, xs, g0, g1,
                                                           Wfc_t, Wfc_s,
                                                           bfc_t, bfc_s, out);
}

// round 2
// speedup vs baseline: 1.6681x; 1.6681x over previous
#include <cuda_runtime.h>
#include <cstdint>

// ---------------------------------------------------------------------------
// Problem constants
// ---------------------------------------------------------------------------
#define Bb   32
#define Nn   512
#define NT   24
#define Hh   8
#define DH   48
#define Ee   384          // H*DH
#define INd  768          // C*NT
#define OUTd 768
#define E3   1152         // 3*E
#define Mrows (Bb*Nn)     // 16384

// ---------------------------------------------------------------------------
// Scratch (device globals; no runtime allocation allowed)
// ---------------------------------------------------------------------------
__device__ float g_qkv_t[(size_t)Mrows * E3];
__device__ float g_qkv_s[(size_t)Mrows * E3];
__device__ float g_xt[(size_t)Mrows * Ee];
__device__ float g_xs[(size_t)Mrows * Ee];
__device__ float g_alpha_in[Bb * 2 * Ee];
__device__ float g_gate0[Bb * Ee];
__device__ float g_gate1[Bb * Ee];

// ---------------------------------------------------------------------------
// tf32 helpers
// ---------------------------------------------------------------------------
__device__ __forceinline__ uint32_t f2tf32(float f) {
    uint32_t o;
    asm("cvt.rna.tf32.f32 %0, %1;" : "=r"(o) : "f"(f));
    return o;
}

__device__ __forceinline__ void mma_tf32(float c[4],
                                         uint32_t a0, uint32_t a1,
                                         uint32_t a2, uint32_t a3,
                                         uint32_t b0, uint32_t b1) {
    asm volatile(
        "mma.sync.aligned.m16n8k8.row.col.f32.tf32.tf32.f32 "
        "{%0,%1,%2,%3}, {%4,%5,%6,%7}, {%8,%9}, {%0,%1,%2,%3};\n"
        : "+f"(c[0]), "+f"(c[1]), "+f"(c[2]), "+f"(c[3])
        : "r"(a0), "r"(a1), "r"(a2), "r"(a3), "r"(b0), "r"(b1));
}

// ---------------------------------------------------------------------------
// tf32 tensor-core GEMM, 128x128 block tile, BK=16, 256 threads (8 warps,
// 2x4 warp grid, 64x32 per warp, m16n8k8).
//
// FUSED=0 : C = A0 @ W0 + bias0                    (A0: Md x Kd, W0: Kd x Nd)
// FUSED=1 : C = (A0*g0[b]) @ W0 + (A1*g1[b]) @ W1 + bias0 + bias1
//           (Kd per pass = Ee; gate indexed by k; 128-row tile within batch)
// ---------------------------------------------------------------------------
template <int FUSED>
__global__ __launch_bounds__(256, 2)
void mma_gemm(const float* __restrict__ A0, const float* __restrict__ A1,
              const float* __restrict__ W0, const float* __restrict__ W1,
              const float* __restrict__ g0, const float* __restrict__ g1,
              const float* __restrict__ bias0, const float* __restrict__ bias1,
              float* __restrict__ C, int Md, int Nd, int Kd)
{
    __shared__ uint32_t As[128][20];   // [m][k], stride 20 -> conflict-free frags
    __shared__ uint32_t Bs[16][132];   // [k][n], stride 132

    const int tid  = threadIdx.x;
    const int lane = tid & 31;
    const int warp = tid >> 5;
    const int g    = lane >> 2;        // 0..7
    const int tig  = lane & 3;         // 0..3
    const int warpM = (warp & 1) * 64;
    const int warpN = (warp >> 1) * 32;

    const int rowBase = blockIdx.y * 128;
    const int colBase = blockIdx.x * 128;
    const int bIdx = rowBase >> 9;     // batch index (row/512), tile-uniform

    // A tile loader: 128x16, float4, two rows apart by 64
    const int aRow  = tid >> 2;        // 0..63
    const int aCol4 = (tid & 3) * 4;   // 0,4,8,12
    // B tile loader: 16x128, float4, two rows apart by 8
    const int bRow  = tid >> 5;        // 0..7
    const int bCol4 = (tid & 31) * 4;  // 0..124

    float acc[4][4][4];
#pragma unroll
    for (int i = 0; i < 4; ++i)
#pragma unroll
        for (int j = 0; j < 4; ++j)
#pragma unroll
            for (int r = 0; r < 4; ++r) acc[i][j][r] = 0.0f;

    const int nPass = FUSED ? 2 : 1;
    for (int pass = 0; pass < nPass; ++pass) {
        const float* A    = (FUSED && pass) ? A1 : A0;
        const float* W    = (FUSED && pass) ? W1 : W0;
        const float* gate = FUSED ? ((pass ? g1 : g0) + bIdx * Ee) : nullptr;

        for (int k0 = 0; k0 < Kd; k0 += 16) {
            // ---- load A tile ----
#pragma unroll
            for (int half = 0; half < 2; ++half) {
                int r = aRow + half * 64;
                float4 a4 = *reinterpret_cast<const float4*>(
                    &A[(size_t)(rowBase + r) * Kd + k0 + aCol4]);
                if (FUSED) {
                    float4 s4 = *reinterpret_cast<const float4*>(&gate[k0 + aCol4]);
                    a4.x *= s4.x; a4.y *= s4.y; a4.z *= s4.z; a4.w *= s4.w;
                }
                uint4 t;
                t.x = f2tf32(a4.x); t.y = f2tf32(a4.y);
                t.z = f2tf32(a4.z); t.w = f2tf32(a4.w);
                *reinterpret_cast<uint4*>(&As[r][aCol4]) = t;
            }
            // ---- load B tile ----
#pragma unroll
            for (int half = 0; half < 2; ++half) {
                int r = bRow + half * 8;
                float4 b4 = *reinterpret_cast<const float4*>(
                    &W[(size_t)(k0 + r) * Nd + colBase + bCol4]);
                uint4 t;
                t.x = f2tf32(b4.x); t.y = f2tf32(b4.y);
                t.z = f2tf32(b4.z); t.w = f2tf32(b4.w);
                *reinterpret_cast<uint4*>(&Bs[r][bCol4]) = t;
            }
            __syncthreads();

            // ---- compute ----
#pragma unroll
            for (int kk = 0; kk < 16; kk += 8) {
                uint32_t af[4][4];
#pragma unroll
                for (int i = 0; i < 4; ++i) {
                    int m0 = warpM + 16 * i;
                    af[i][0] = As[m0 + g][kk + tig];
                    af[i][1] = As[m0 + g + 8][kk + tig];
                    af[i][2] = As[m0 + g][kk + tig + 4];
                    af[i][3] = As[m0 + g + 8][kk + tig + 4];
                }
                uint32_t bf[4][2];
#pragma unroll
                for (int j = 0; j < 4; ++j) {
                    int n0 = warpN + 8 * j;
                    bf[j][0] = Bs[kk + tig][n0 + g];
                    bf[j][1] = Bs[kk + tig + 4][n0 + g];
                }
#pragma unroll
                for (int i = 0; i < 4; ++i)
#pragma unroll
                    for (int j = 0; j < 4; ++j)
                        mma_tf32(acc[i][j], af[i][0], af[i][1], af[i][2],
                                 af[i][3], bf[j][0], bf[j][1]);
            }
            __syncthreads();
        }
    }

    // ---- epilogue ----
#pragma unroll
    for (int i = 0; i < 4; ++i) {
#pragma unroll
        for (int j = 0; j < 4; ++j) {
            int col = colBase + warpN + 8 * j + 2 * tig;
            float bsum0, bsum1;
            if (FUSED) {
                bsum0 = bias0[col] + bias1[col];
                bsum1 = bias0[col + 1] + bias1[col + 1];
            } else {
                bsum0 = bias0[col];
                bsum1 = bias0[col + 1];
            }
            int row0 = rowBase + warpM + 16 * i + g;
            float2 o0 = make_float2(acc[i][j][0] + bsum0, acc[i][j][1] + bsum1);
            *reinterpret_cast<float2*>(&C[(size_t)row0 * Nd + col]) = o0;
            float2 o1 = make_float2(acc[i][j][2] + bsum0, acc[i][j][3] + bsum1);
            *reinterpret_cast<float2*>(&C[(size_t)(row0 + 8) * Nd + col]) = o1;
        }
    }
}

// ---------------------------------------------------------------------------
// Temporal attention (flash-style, branchy max-update so the common path
// is 48 FMA + 1 exp per key instead of 96 FMA + 2 exp).
// grid (N/128, H, B), block 128. Thread owns one query row.
// ---------------------------------------------------------------------------
__global__ __launch_bounds__(128)
void temporal_attn(const float* __restrict__ qkv, float* __restrict__ xt)
{
    __shared__ float Ks[64 * DH];
    __shared__ float Vs[64 * DH];

    const int b = blockIdx.z, h = blockIdx.y;
    const int n = blockIdx.x * 128 + threadIdx.x;
    const int tid = threadIdx.x;
    const float scale = 0.14433756729740643f; // 1/sqrt(48)

    float q[DH];
    {
        const float* qp = qkv + ((size_t)(b * Nn + n)) * E3 + h * DH;
#pragma unroll
        for (int d = 0; d < DH; ++d) q[d] = qp[d] * scale;
    }

    float o[DH];
#pragma unroll
    for (int d = 0; d < DH; ++d) o[d] = 0.0f;
    float m = -1e30f, l = 0.0f;

    for (int kt = 0; kt < Nn; kt += 64) {
        for (int i = tid; i < 64 * DH; i += 128) {
            int r = i / DH, c = i - r * DH;
            size_t base = ((size_t)(b * Nn + kt + r)) * E3 + h * DH + c;
            Ks[i] = qkv[base + Ee];
            Vs[i] = qkv[base + 2 * Ee];
        }
        __syncthreads();

#pragma unroll 2
        for (int j = 0; j < 64; ++j) {
            const float* kr = &Ks[j * DH];
            float s = 0.0f;
#pragma unroll
            for (int d = 0; d < DH; ++d) s = fmaf(q[d], kr[d], s);
            const float* vr = &Vs[j * DH];
            if (s <= m) {
                float p = __expf(s - m);
                l += p;
#pragma unroll
                for (int d = 0; d < DH; ++d) o[d] = fmaf(p, vr[d], o[d]);
            } else {
                float corr = __expf(m - s);
                l = fmaf(l, corr, 1.0f);
#pragma unroll
                for (int d = 0; d < DH; ++d) o[d] = fmaf(o[d], corr, vr[d]);
                m = s;
            }
        }
        __syncthreads();
    }

    float inv = 1.0f / l;
    float* op = xt + ((size_t)(b * Nn + n)) * Ee + h * DH;
#pragma unroll
    for (int d = 0; d < DH; ++d) op[d] = o[d] * inv;
}

// ---------------------------------------------------------------------------
// Spatial attention: per g = b*n, per head: q,k,v are (cs=2, nt=24).
// block = 256 (8 warps, warp = head), grid = 16384
// ---------------------------------------------------------------------------
__global__ __launch_bounds__(256)
void spatial_attn(const float* __restrict__ qkv, float* __restrict__ xs)
{
    __shared__ float sh[8][3 * DH];
    const int gBlk = blockIdx.x;
    const int w = threadIdx.x >> 5, lane = threadIdx.x & 31;

    const float* base = qkv + (size_t)gBlk * E3 + w * DH;
    for (int i = lane; i < 3 * DH; i += 32) {
        int sec = i / DH, idx = i - sec * DH;
        sh[w][i] = base[sec * Ee + idx];
    }
    __syncwarp();

    if (lane < NT) {
        const float* q = sh[w];
        const float* k = sh[w] + DH;
        const float* v = sh[w] + 2 * DH;
        float q0 = q[lane], q1 = q[NT + lane];
        float s[NT];
        float mx = -1e30f;
#pragma unroll
        for (int u = 0; u < NT; ++u) {
            s[u] = fmaf(q1, k[NT + u], q0 * k[u]);
            mx = fmaxf(mx, s[u]);
        }
        float sum = 0.0f;
#pragma unroll
        for (int u = 0; u < NT; ++u) { s[u] = __expf(s[u] - mx); sum += s[u]; }
        float inv = 1.0f / sum;
        float o0 = 0.0f, o1 = 0.0f;
#pragma unroll
        for (int u = 0; u < NT; ++u) {
            o0 = fmaf(s[u], v[u], o0);
            o1 = fmaf(s[u], v[NT + u], o1);
        }
        float* op = xs + (size_t)gBlk * Ee + w * DH;
        op[lane]      = o0 * inv;
        op[NT + lane] = o1 * inv;
    }
}

// ---------------------------------------------------------------------------
// Mean over frames of concat([x_t, x_s]) -> (B, 768)
// ---------------------------------------------------------------------------
__global__ __launch_bounds__(256)
void mean_concat(const float* __restrict__ xt, const float* __restrict__ xs,
                 float* __restrict__ alphaIn)
{
    const int b = blockIdx.x, tid = threadIdx.x;
#pragma unroll
    for (int jj = 0; jj < 3; ++jj) {
        int j = tid + jj * 256;
        const float* src = (j < Ee)
            ? xt + (size_t)b * Nn * Ee + j
            : xs + (size_t)b * Nn * Ee + (j - Ee);
        float acc = 0.0f;
        for (int n = 0; n < Nn; ++n) acc += src[(size_t)n * Ee];
        alphaIn[b * 2 * Ee + j] = acc * (1.0f / (float)Nn);
    }
}

// ---------------------------------------------------------------------------
// Gating: row = alphaIn[b] @ Wts + bts; pairwise softmax over (E,2).
// ---------------------------------------------------------------------------
__global__ __launch_bounds__(768)
void gate_kernel(const float* __restrict__ alphaIn, const float* __restrict__ Wts,
                 const float* __restrict__ bts,
                 float* __restrict__ g0, float* __restrict__ g1)
{
    __shared__ float a[768];
    __shared__ float val[768];
    const int b = blockIdx.x, t = threadIdx.x;
    a[t] = alphaIn[b * 768 + t];
    __syncthreads();
    float acc = bts[t];
    for (int k = 0; k < 768; ++k)
        acc = fmaf(a[k], Wts[(size_t)k * 768 + t], acc);
    val[t] = acc;
    __syncthreads();
    if (t < Ee) {
        float v0 = val[2 * t], v1 = val[2 * t + 1];
        float mx = fmaxf(v0, v1);
        float e0 = __expf(v0 - mx), e1 = __expf(v1 - mx);
        float inv = 1.0f / (e0 + e1);
        g0[b * Ee + t] = e0 * inv;
        g1[b * Ee + t] = e1 * inv;
    }
}

// ---------------------------------------------------------------------------
// Launch
// ---------------------------------------------------------------------------
extern "C" void kernel_launch(void* const* d_in, const int* in_sizes, int n_in,
                              void* d_out, int out_size)
{
    const float* x      = (const float*)d_in[0];
    const float* Wqkv_t = (const float*)d_in[1];
    const float* bqkv_t = (const float*)d_in[2];
    const float* Wqkv_s = (const float*)d_in[3];
    const float* bqkv_s = (const float*)d_in[4];
    const float* Wts    = (const float*)d_in[5];
    const float* bts    = (const float*)d_in[6];
    const float* Wfc_t  = (const float*)d_in[7];
    const float* bfc_t  = (const float*)d_in[8];
    const float* Wfc_s  = (const float*)d_in[9];
    const float* bfc_s  = (const float*)d_in[10];
    float* out = (float*)d_out;

    float *qkvT, *qkvS, *xt, *xs, *alphaIn, *g0, *g1;
    cudaGetSymbolAddress((void**)&qkvT,    g_qkv_t);
    cudaGetSymbolAddress((void**)&qkvS,    g_qkv_s);
    cudaGetSymbolAddress((void**)&xt,      g_xt);
    cudaGetSymbolAddress((void**)&xs,      g_xs);
    cudaGetSymbolAddress((void**)&alphaIn, g_alpha_in);
    cudaGetSymbolAddress((void**)&g0,      g_gate0);
    cudaGetSymbolAddress((void**)&g1,      g_gate1);

    // QKV projections (tensor cores, tf32)
    mma_gemm<0><<<dim3(E3 / 128, Mrows / 128), 256>>>(
        x, nullptr, Wqkv_t, nullptr, nullptr, nullptr, bqkv_t, nullptr,
        qkvT, Mrows, E3, INd);
    mma_gemm<0><<<dim3(E3 / 128, Mrows / 128), 256>>>(
        x, nullptr, Wqkv_s, nullptr, nullptr, nullptr, bqkv_s, nullptr,
        qkvS, Mrows, E3, INd);
    // Attentions
    temporal_attn<<<dim3(Nn / 128, Hh, Bb), 128>>>(qkvT, xt);
    spatial_attn<<<Mrows, 256>>>(qkvS, xs);
    // Gating
    mean_concat<<<Bb, 256>>>(xt, xs, alphaIn);
    gate_kernel<<<Bb, 768>>>(alphaIn, Wts, bts, g0, g1);
    // Fused gated output projection (tensor cores, tf32)
    mma_gemm<1><<<dim3(OUTd / 128, Mrows / 128), 256>>>(
        xt, xs, Wfc_t, Wfc_s, g0, g1, bfc_t, bfc_s,
        out, Mrows, OUTd, Ee);
}

// round 4
// speedup vs baseline: 2.3948x; 1.4357x over previous
#include <cuda_runtime.h>
#include <cstdint>

// ---------------------------------------------------------------------------
// Problem constants
// ---------------------------------------------------------------------------
#define Bb   32
#define Nn   512
#define NT   24
#define Hh   8
#define DH   48
#define Ee   384          // H*DH
#define INd  768          // C*NT
#define OUTd 768
#define E3   1152         // 3*E
#define Mrows (Bb*Nn)     // 16384

// ---------------------------------------------------------------------------
// Scratch (device globals)
// ---------------------------------------------------------------------------
__device__ float g_qkv_t[(size_t)Mrows * E3];
__device__ float g_qkv_s[(size_t)Mrows * E3];
__device__ float g_xt[(size_t)Mrows * Ee];
__device__ float g_xs[(size_t)Mrows * Ee];
__device__ float g_alpha_in[Bb * 2 * Ee];
__device__ float g_gate0[Bb * Ee];
__device__ float g_gate1[Bb * Ee];

// ---------------------------------------------------------------------------
// tf32 / cp.async helpers
// ---------------------------------------------------------------------------
__device__ __forceinline__ uint32_t f2tf32(float f) {
    uint32_t o;
    asm("cvt.rna.tf32.f32 %0, %1;" : "=r"(o) : "f"(f));
    return o;
}

__device__ __forceinline__ void mma_tf32(float c[4],
                                         uint32_t a0, uint32_t a1,
                                         uint32_t a2, uint32_t a3,
                                         uint32_t b0, uint32_t b1) {
    asm volatile(
        "mma.sync.aligned.m16n8k8.row.col.f32.tf32.tf32.f32 "
        "{%0,%1,%2,%3}, {%4,%5,%6,%7}, {%8,%9}, {%0,%1,%2,%3};\n"
        : "+f"(c[0]), "+f"(c[1]), "+f"(c[2]), "+f"(c[3])
        : "r"(a0), "r"(a1), "r"(a2), "r"(a3), "r"(b0), "r"(b1));
}

__device__ __forceinline__ void cp_async16(void* smem_dst, const void* gmem_src) {
    uint32_t d = (uint32_t)__cvta_generic_to_shared(smem_dst);
    asm volatile("cp.async.cg.shared.global [%0], [%1], 16;\n"
                 :: "r"(d), "l"(gmem_src));
}
__device__ __forceinline__ void cp_async_commit() {
    asm volatile("cp.async.commit_group;\n");
}
__device__ __forceinline__ void cp_async_wait_all() {
    asm volatile("cp.async.wait_group 0;\n");
}

// ---------------------------------------------------------------------------
// tf32 GEMM, 128x128 tile, BK=16, 256 threads, cp.async double buffered.
// FUSED=0 : C = A0 @ W0 + bias0
// FUSED=1 : C = (A0*g0[b]) @ W0 + (A1*g1[b]) @ W1 + bias0 + bias1
//           gate applied to B rows: (A*diag(g))@W == A@(diag(g)W)
// ---------------------------------------------------------------------------
template <int FUSED>
__global__ __launch_bounds__(256, 2)
void mma_gemm(const float* __restrict__ A0, const float* __restrict__ A1,
              const float* __restrict__ W0, const float* __restrict__ W1,
              const float* __restrict__ g0p, const float* __restrict__ g1p,
              const float* __restrict__ bias0, const float* __restrict__ bias1,
              float* __restrict__ C, int Md, int Nd, int Kd)
{
    __shared__ float As[2][128][20];
    __shared__ float Bs[2][16][132];

    const int tid  = threadIdx.x;
    const int lane = tid & 31;
    const int warp = tid >> 5;
    const int g    = lane >> 2;
    const int tig  = lane & 3;
    const int warpM = (warp & 1) * 64;
    const int warpN = (warp >> 1) * 32;

    const int rowBase = blockIdx.y * 128;
    const int colBase = blockIdx.x * 128;
    const int bIdx = rowBase >> 9;

    const int aRow  = tid >> 2;        // 0..63 (+64)
    const int aCol4 = (tid & 3) * 4;
    const int bRow  = tid >> 5;        // 0..7 (+8)
    const int bCol4 = (tid & 31) * 4;

    const int perPass = Kd / 16;
    const int nIter = (FUSED ? 2 : 1) * perPass;

    auto issueLoad = [&](int it, int buf) {
        int pass = FUSED ? (it / perPass) : 0;
        int k0 = (FUSED ? (it % perPass) : it) * 16;
        const float* A = (FUSED && pass) ? A1 : A0;
        const float* W = (FUSED && pass) ? W1 : W0;
#pragma unroll
        for (int half = 0; half < 2; ++half) {
            int r = aRow + half * 64;
            cp_async16(&As[buf][r][aCol4],
                       &A[(size_t)(rowBase + r) * Kd + k0 + aCol4]);
        }
#pragma unroll
        for (int half = 0; half < 2; ++half) {
            int r = bRow + half * 8;
            cp_async16(&Bs[buf][r][bCol4],
                       &W[(size_t)(k0 + r) * Nd + colBase + bCol4]);
        }
        cp_async_commit();
    };

    float acc[4][4][4];
#pragma unroll
    for (int i = 0; i < 4; ++i)
#pragma unroll
        for (int j = 0; j < 4; ++j)
#pragma unroll
            for (int r = 0; r < 4; ++r) acc[i][j][r] = 0.0f;

    issueLoad(0, 0);
    int buf = 0;

    for (int it = 0; it < nIter; ++it) {
        cp_async_wait_all();
        __syncthreads();
        if (it + 1 < nIter) issueLoad(it + 1, buf ^ 1);

        const float* gate = nullptr;
        int kBase = 0;
        if (FUSED) {
            int pass = it / perPass;
            kBase = (it % perPass) * 16;
            gate = (pass ? g1p : g0p) + bIdx * Ee;
        }

#pragma unroll
        for (int kk = 0; kk < 16; kk += 8) {
            uint32_t af[4][4];
#pragma unroll
            for (int i = 0; i < 4; ++i) {
                int m0 = warpM + 16 * i;
                af[i][0] = f2tf32(As[buf][m0 + g][kk + tig]);
                af[i][1] = f2tf32(As[buf][m0 + g + 8][kk + tig]);
                af[i][2] = f2tf32(As[buf][m0 + g][kk + tig + 4]);
                af[i][3] = f2tf32(As[buf][m0 + g + 8][kk + tig + 4]);
            }
            float gv0 = 1.0f, gv1 = 1.0f;
            if (FUSED) {
                gv0 = gate[kBase + kk + tig];
                gv1 = gate[kBase + kk + tig + 4];
            }
            uint32_t bf[4][2];
#pragma unroll
            for (int j = 0; j < 4; ++j) {
                int n0 = warpN + 8 * j;
                float v0 = Bs[buf][kk + tig][n0 + g];
                float v1 = Bs[buf][kk + tig + 4][n0 + g];
                if (FUSED) { v0 *= gv0; v1 *= gv1; }
                bf[j][0] = f2tf32(v0);
                bf[j][1] = f2tf32(v1);
            }
#pragma unroll
            for (int i = 0; i < 4; ++i)
#pragma unroll
                for (int j = 0; j < 4; ++j)
                    mma_tf32(acc[i][j], af[i][0], af[i][1], af[i][2],
                             af[i][3], bf[j][0], bf[j][1]);
        }
        buf ^= 1;
    }
    __syncthreads();

#pragma unroll
    for (int i = 0; i < 4; ++i) {
#pragma unroll
        for (int j = 0; j < 4; ++j) {
            int col = colBase + warpN + 8 * j + 2 * tig;
            float bsum0, bsum1;
            if (FUSED) {
                bsum0 = bias0[col] + bias1[col];
                bsum1 = bias0[col + 1] + bias1[col + 1];
            } else {
                bsum0 = bias0[col];
                bsum1 = bias0[col + 1];
            }
            int row0 = rowBase + warpM + 16 * i + g;
            float2 o0 = make_float2(acc[i][j][0] + bsum0, acc[i][j][1] + bsum1);
            *reinterpret_cast<float2*>(&C[(size_t)row0 * Nd + col]) = o0;
            float2 o1 = make_float2(acc[i][j][2] + bsum0, acc[i][j][3] + bsum1);
            *reinterpret_cast<float2*>(&C[(size_t)(row0 + 8) * Nd + col]) = o1;
        }
    }
}

// ---------------------------------------------------------------------------
// Flash temporal attention on tensor cores (tf32, fp32 accumulate).
// CTA = (64 q-rows, head, batch); 4 warps; warp owns 16 q-rows.
// Online softmax in registers; P round-trips through smem (reusing Q buffer).
// ---------------------------------------------------------------------------
__global__ __launch_bounds__(128)
void flash_tattn(const float* __restrict__ qkv, float* __restrict__ xt)
{
    __shared__ float QP[64][68];   // Q staging, then P
    __shared__ float Ks[64][52];   // K chunk [key][dim]
    __shared__ float Vt[48][68];   // V chunk transposed [dim][key]

    const int b = blockIdx.z, h = blockIdx.y;
    const int q0 = blockIdx.x * 64;
    const int tid = threadIdx.x;
    const int warp = tid >> 5, lane = tid & 31;
    const int g = lane >> 2, tig = lane & 3;
    const int m0 = warp * 16;
    const float scale = 0.14433756729740643f; // 1/sqrt(48)

    const float* base = qkv + (size_t)(b * Nn) * E3 + h * DH;

    // ---- stage Q (scaled) ----
    for (int i = tid; i < 64 * 12; i += 128) {
        int r = i / 12, f = i % 12;
        float4 v = *reinterpret_cast<const float4*>(
            &base[(size_t)(q0 + r) * E3 + 4 * f]);
        v.x *= scale; v.y *= scale; v.z *= scale; v.w *= scale;
        *reinterpret_cast<float4*>(&QP[r][4 * f]) = v;
    }
    __syncthreads();

    // ---- Q fragments (held in registers for whole kernel) ----
    uint32_t qf[6][4];
#pragma unroll
    for (int kc = 0; kc < 6; ++kc) {
        qf[kc][0] = f2tf32(QP[m0 + g][8 * kc + tig]);
        qf[kc][1] = f2tf32(QP[m0 + g + 8][8 * kc + tig]);
        qf[kc][2] = f2tf32(QP[m0 + g][8 * kc + tig + 4]);
        qf[kc][3] = f2tf32(QP[m0 + g + 8][8 * kc + tig + 4]);
    }
    __syncthreads();   // QP now reusable as P (per-warp rows only)

    float of[6][4];
#pragma unroll
    for (int nb = 0; nb < 6; ++nb)
#pragma unroll
        for (int r = 0; r < 4; ++r) of[nb][r] = 0.0f;
    float mr0 = -1e30f, mr1 = -1e30f, l0 = 0.0f, l1 = 0.0f;

    for (int c0 = 0; c0 < Nn; c0 += 64) {
        // ---- load K chunk + V^T chunk ----
        for (int i = tid; i < 64 * 12; i += 128) {
            int r = i / 12, f = i % 12;
            const float* src = &base[(size_t)(c0 + r) * E3 + 4 * f];
            float4 kv = *reinterpret_cast<const float4*>(src + Ee);
            *reinterpret_cast<float4*>(&Ks[r][4 * f]) = kv;
            float4 vv = *reinterpret_cast<const float4*>(src + 2 * Ee);
            Vt[4 * f + 0][r] = vv.x;
            Vt[4 * f + 1][r] = vv.y;
            Vt[4 * f + 2][r] = vv.z;
            Vt[4 * f + 3][r] = vv.w;
        }
        __syncthreads();

        // ---- S = Q K^T (8 key-blocks of 8) ----
        float s[8][4];
#pragma unroll
        for (int jb = 0; jb < 8; ++jb)
#pragma unroll
            for (int r = 0; r < 4; ++r) s[jb][r] = 0.0f;
#pragma unroll
        for (int kc = 0; kc < 6; ++kc) {
#pragma unroll
            for (int jb = 0; jb < 8; ++jb) {
                uint32_t b0 = f2tf32(Ks[8 * jb + g][8 * kc + tig]);
                uint32_t b1 = f2tf32(Ks[8 * jb + g][8 * kc + tig + 4]);
                mma_tf32(s[jb], qf[kc][0], qf[kc][1], qf[kc][2], qf[kc][3],
                         b0, b1);
            }
        }

        // ---- online softmax ----
        float cm0 = -1e30f, cm1 = -1e30f;
#pragma unroll
        for (int jb = 0; jb < 8; ++jb) {
            cm0 = fmaxf(cm0, fmaxf(s[jb][0], s[jb][1]));
            cm1 = fmaxf(cm1, fmaxf(s[jb][2], s[jb][3]));
        }
        cm0 = fmaxf(cm0, __shfl_xor_sync(0xffffffffu, cm0, 1));
        cm0 = fmaxf(cm0, __shfl_xor_sync(0xffffffffu, cm0, 2));
        cm1 = fmaxf(cm1, __shfl_xor_sync(0xffffffffu, cm1, 1));
        cm1 = fmaxf(cm1, __shfl_xor_sync(0xffffffffu, cm1, 2));
        float nm0 = fmaxf(mr0, cm0), nm1 = fmaxf(mr1, cm1);
        float corr0 = __expf(mr0 - nm0), corr1 = __expf(mr1 - nm1);
        float rs0 = 0.0f, rs1 = 0.0f;
#pragma unroll
        for (int jb = 0; jb < 8; ++jb) {
            s[jb][0] = __expf(s[jb][0] - nm0);
            s[jb][1] = __expf(s[jb][1] - nm0);
            rs0 += s[jb][0] + s[jb][1];
            s[jb][2] = __expf(s[jb][2] - nm1);
            s[jb][3] = __expf(s[jb][3] - nm1);
            rs1 += s[jb][2] + s[jb][3];
        }
        rs0 += __shfl_xor_sync(0xffffffffu, rs0, 1);
        rs0 += __shfl_xor_sync(0xffffffffu, rs0, 2);
        rs1 += __shfl_xor_sync(0xffffffffu, rs1, 1);
        rs1 += __shfl_xor_sync(0xffffffffu, rs1, 2);
        l0 = l0 * corr0 + rs0;
        l1 = l1 * corr1 + rs1;
        mr0 = nm0; mr1 = nm1;
#pragma unroll
        for (int nb = 0; nb < 6; ++nb) {
            of[nb][0] *= corr0; of[nb][1] *= corr0;
            of[nb][2] *= corr1; of[nb][3] *= corr1;
        }

        // ---- write P to smem (own warp rows), then O += P V ----
#pragma unroll
        for (int jb = 0; jb < 8; ++jb) {
            *reinterpret_cast<float2*>(&QP[m0 + g][8 * jb + 2 * tig]) =
                make_float2(s[jb][0], s[jb][1]);
            *reinterpret_cast<float2*>(&QP[m0 + g + 8][8 * jb + 2 * tig]) =
                make_float2(s[jb][2], s[jb][3]);
        }
        __syncwarp();

#pragma unroll
        for (int pc = 0; pc < 8; ++pc) {
            uint32_t pa0 = f2tf32(QP[m0 + g][8 * pc + tig]);
            uint32_t pa1 = f2tf32(QP[m0 + g + 8][8 * pc + tig]);
            uint32_t pa2 = f2tf32(QP[m0 + g][8 * pc + tig + 4]);
            uint32_t pa3 = f2tf32(QP[m0 + g + 8][8 * pc + tig + 4]);
#pragma unroll
            for (int nb = 0; nb < 6; ++nb) {
                uint32_t b0 = f2tf32(Vt[8 * nb + g][8 * pc + tig]);
                uint32_t b1 = f2tf32(Vt[8 * nb + g][8 * pc + tig + 4]);
                mma_tf32(of[nb], pa0, pa1, pa2, pa3, b0, b1);
            }
        }
        __syncthreads();   // Ks/Vt consumed; next chunk may overwrite
    }

    // ---- epilogue ----
    float inv0 = 1.0f / l0, inv1 = 1.0f / l1;
    float* orow0 = xt + (size_t)(b * Nn + q0 + m0 + g) * Ee + h * DH;
    float* orow1 = orow0 + (size_t)8 * Ee;
#pragma unroll
    for (int nb = 0; nb < 6; ++nb) {
        int col = 8 * nb + 2 * tig;
        *reinterpret_cast<float2*>(&orow0[col]) =
            make_float2(of[nb][0] * inv0, of[nb][1] * inv0);
        *reinterpret_cast<float2*>(&orow1[col]) =
            make_float2(of[nb][2] * inv1, of[nb][3] * inv1);
    }
}

// ---------------------------------------------------------------------------
// Spatial attention
// ---------------------------------------------------------------------------
__global__ __launch_bounds__(256)
void spatial_attn(const float* __restrict__ qkv, float* __restrict__ xs)
{
    __shared__ float sh[8][3 * DH];
    const int gBlk = blockIdx.x;
    const int w = threadIdx.x >> 5, lane = threadIdx.x & 31;

    const float* base = qkv + (size_t)gBlk * E3 + w * DH;
    for (int i = lane; i < 3 * DH; i += 32) {
        int sec = i / DH, idx = i - sec * DH;
        sh[w][i] = base[sec * Ee + idx];
    }
    __syncwarp();

    if (lane < NT) {
        const float* q = sh[w];
        const float* k = sh[w] + DH;
        const float* v = sh[w] + 2 * DH;
        float q0 = q[lane], q1 = q[NT + lane];
        float s[NT];
        float mx = -1e30f;
#pragma unroll
        for (int u = 0; u < NT; ++u) {
            s[u] = fmaf(q1, k[NT + u], q0 * k[u]);
            mx = fmaxf(mx, s[u]);
        }
        float sum = 0.0f;
#pragma unroll
        for (int u = 0; u < NT; ++u) { s[u] = __expf(s[u] - mx); sum += s[u]; }
        float inv = 1.0f / sum;
        float o0 = 0.0f, o1 = 0.0f;
#pragma unroll
        for (int u = 0; u < NT; ++u) {
            o0 = fmaf(s[u], v[u], o0);
            o1 = fmaf(s[u], v[NT + u], o1);
        }
        float* op = xs + (size_t)gBlk * Ee + w * DH;
        op[lane]      = o0 * inv;
        op[NT + lane] = o1 * inv;
    }
}

// ---------------------------------------------------------------------------
// Mean over frames of concat([x_t, x_s]) -> (B, 768). grid (B, 6) x 128.
// ---------------------------------------------------------------------------
__global__ __launch_bounds__(128)
void mean_concat(const float* __restrict__ xt, const float* __restrict__ xs,
                 float* __restrict__ alphaIn)
{
    const int b = blockIdx.x;
    const int j = blockIdx.y * 128 + threadIdx.x;  // 0..767
    const float* src = (j < Ee)
        ? xt + (size_t)b * Nn * Ee + j
        : xs + (size_t)b * Nn * Ee + (j - Ee);
    float acc = 0.0f;
#pragma unroll 8
    for (int n = 0; n < Nn; ++n) acc += src[(size_t)n * Ee];
    alphaIn[b * 2 * Ee + j] = acc * (1.0f / (float)Nn);
}

// ---------------------------------------------------------------------------
// Gating
// ---------------------------------------------------------------------------
__global__ __launch_bounds__(768)
void gate_kernel(const float* __restrict__ alphaIn, const float* __restrict__ Wts,
                 const float* __restrict__ bts,
                 float* __restrict__ g0, float* __restrict__ g1)
{
    __shared__ float a[768];
    __shared__ float val[768];
    const int b = blockIdx.x, t = threadIdx.x;
    a[t] = alphaIn[b * 768 + t];
    __syncthreads();
    float acc = bts[t];
    for (int k = 0; k < 768; ++k)
        acc = fmaf(a[k], Wts[(size_t)k * 768 + t], acc);
    val[t] = acc;
    __syncthreads();
    if (t < Ee) {
        float v0 = val[2 * t], v1 = val[2 * t + 1];
        float mx = fmaxf(v0, v1);
        float e0 = __expf(v0 - mx), e1 = __expf(v1 - mx);
        float inv = 1.0f / (e0 + e1);
        g0[b * Ee + t] = e0 * inv;
        g1[b * Ee + t] = e1 * inv;
    }
}

// ---------------------------------------------------------------------------
// Launch
// ---------------------------------------------------------------------------
extern "C" void kernel_launch(void* const* d_in, const int* in_sizes, int n_in,
                              void* d_out, int out_size)
{
    const float* x      = (const float*)d_in[0];
    const float* Wqkv_t = (const float*)d_in[1];
    const float* bqkv_t = (const float*)d_in[2];
    const float* Wqkv_s = (const float*)d_in[3];
    const float* bqkv_s = (const float*)d_in[4];
    const float* Wts    = (const float*)d_in[5];
    const float* bts    = (const float*)d_in[6];
    const float* Wfc_t  = (const float*)d_in[7];
    const float* bfc_t  = (const float*)d_in[8];
    const float* Wfc_s  = (const float*)d_in[9];
    const float* bfc_s  = (const float*)d_in[10];
    float* out = (float*)d_out;

    float *qkvT, *qkvS, *xt, *xs, *alphaIn, *g0, *g1;
    cudaGetSymbolAddress((void**)&qkvT,    g_qkv_t);
    cudaGetSymbolAddress((void**)&qkvS,    g_qkv_s);
    cudaGetSymbolAddress((void**)&xt,      g_xt);
    cudaGetSymbolAddress((void**)&xs,      g_xs);
    cudaGetSymbolAddress((void**)&alphaIn, g_alpha_in);
    cudaGetSymbolAddress((void**)&g0,      g_gate0);
    cudaGetSymbolAddress((void**)&g1,      g_gate1);

    // QKV projections
    mma_gemm<0><<<dim3(E3 / 128, Mrows / 128), 256>>>(
        x, nullptr, Wqkv_t, nullptr, nullptr, nullptr, bqkv_t, nullptr,
        qkvT, Mrows, E3, INd);
    mma_gemm<0><<<dim3(E3 / 128, Mrows / 128), 256>>>(
        x, nullptr, Wqkv_s, nullptr, nullptr, nullptr, bqkv_s, nullptr,
        qkvS, Mrows, E3, INd);
    // Attentions
    flash_tattn<<<dim3(Nn / 64, Hh, Bb), 128>>>(qkvT, xt);
    spatial_attn<<<Mrows, 256>>>(qkvS, xs);
    // Gating
    mean_concat<<<dim3(Bb, 6), 128>>>(xt, xs, alphaIn);
    gate_kernel<<<Bb, 768>>>(alphaIn, Wts, bts, g0, g1);
    // Fused gated output projection
    mma_gemm<1><<<dim3(OUTd / 128, Mrows / 128), 256>>>(
        xt, xs, Wfc_t, Wfc_s, g0, g1, bfc_t, bfc_s,
        out, Mrows, OUTd, Ee);
}